// round 2
// baseline (speedup 1.0000x reference)
#include <cuda_runtime.h>
#include <math.h>

#define NS_N 2048
#define NS_B 16
#define WARPS_PER_BLOCK 8
#define ROWS_PER_WARP 4
#define ROWS_PER_BLOCK (WARPS_PER_BLOCK * ROWS_PER_WARP)   // 32

// scratch (allocation-free rule: __device__ globals)
__device__ double g_bsum_d[NS_B * NS_N];
__device__ float  g_bsum_f[NS_B * NS_N];

// ---------------------------------------------------------------------------
// Kernel 1: Bsum[b][j] = sum_k |s[b][j] - s[b][k]|, accumulated in double.
// Inner groups of 4 summed in f32 (error ~1e-6), group sums added in f64.
// grid: (N/256, B), block: 256
// ---------------------------------------------------------------------------
__global__ __launch_bounds__(256) void ns_bsum_kernel(const float* __restrict__ scores) {
    __shared__ float s[NS_N];
    const int b = blockIdx.y;
    const float* sp = scores + b * NS_N;
    for (int k = threadIdx.x; k < NS_N; k += 256)
        s[k] = sp[k];
    __syncthreads();

    const int j = blockIdx.x * 256 + threadIdx.x;
    const float sj = s[j];
    double acc = 0.0;
#pragma unroll 4
    for (int k = 0; k < NS_N; k += 4) {
        float d0 = fabsf(sj - s[k + 0]);
        float d1 = fabsf(sj - s[k + 1]);
        float d2 = fabsf(sj - s[k + 2]);
        float d3 = fabsf(sj - s[k + 3]);
        acc += (double)((d0 + d1) + (d2 + d3));
    }
    g_bsum_d[b * NS_N + j] = acc;
    g_bsum_f[b * NS_N + j] = (float)acc;
}

// ---------------------------------------------------------------------------
// Kernel 2: out[b][i][j] = softmax_j( scale_i * s[b][j] - Bsum[b][j] )
//   scale_i = (N - 1 - 2*i)
// One warp per output row. Pass A: approximate f32 row max for all 4 rows
// (max precision is irrelevant: a row-constant shift cancels in softmax).
// Pass B: x - m in DOUBLE (DFMA + DADD), so the elementwise logit variation
// is exact; convert the small result to f32 and exp.
// grid: (N / ROWS_PER_BLOCK, B), block: 256 (8 warps)
// ---------------------------------------------------------------------------
__global__ __launch_bounds__(256) void ns_softmax_kernel(const float* __restrict__ scores,
                                                         float* __restrict__ out) {
    __shared__ float  sh_s [NS_N];
    __shared__ float  sh_bf[NS_N];
    __shared__ double sh_bd[NS_N];

    const int b = blockIdx.y;
    {
        const float4* sp4 = (const float4*)(scores + b * NS_N);
        const float4* bf4 = (const float4*)(g_bsum_f + b * NS_N);
        const double2* bd2 = (const double2*)(g_bsum_d + b * NS_N);
        float4*  ss4 = (float4*)sh_s;
        float4*  sb4 = (float4*)sh_bf;
        double2* sd2 = (double2*)sh_bd;
        for (int k = threadIdx.x; k < NS_N / 4; k += 256) {
            ss4[k] = sp4[k];
            sb4[k] = bf4[k];
            sd2[2 * k + 0] = bd2[2 * k + 0];
            sd2[2 * k + 1] = bd2[2 * k + 1];
        }
    }
    __syncthreads();

    const int warp = threadIdx.x >> 5;
    const int lane = threadIdx.x & 31;
    const float4* s4 = (const float4*)sh_s;
    const float4* b4 = (const float4*)sh_bf;
    const double2* d2 = (const double2*)sh_bd;

    const int i0 = blockIdx.x * ROWS_PER_BLOCK + warp;   // rows: i0 + r*8
    float scale[ROWS_PER_WARP];
    float mx[ROWS_PER_WARP];
#pragma unroll
    for (int r = 0; r < ROWS_PER_WARP; ++r) {
        scale[r] = (float)(NS_N - 1 - 2 * (i0 + r * WARPS_PER_BLOCK));
        mx[r] = -INFINITY;
    }

    // ---- pass A: f32 row maxima, all 4 rows share each load ----
#pragma unroll
    for (int c = 0; c < 16; ++c) {
        const int idx = c * 32 + lane;
        const float4 sv = s4[idx];
        const float4 bv = b4[idx];
#pragma unroll
        for (int r = 0; r < ROWS_PER_WARP; ++r) {
            const float sc = scale[r];
            float t0 = fmaf(sc, sv.x, -bv.x);
            float t1 = fmaf(sc, sv.y, -bv.y);
            float t2 = fmaf(sc, sv.z, -bv.z);
            float t3 = fmaf(sc, sv.w, -bv.w);
            mx[r] = fmaxf(mx[r], fmaxf(fmaxf(t0, t1), fmaxf(t2, t3)));
        }
    }
#pragma unroll
    for (int r = 0; r < ROWS_PER_WARP; ++r)
#pragma unroll
        for (int o = 16; o > 0; o >>= 1)
            mx[r] = fmaxf(mx[r], __shfl_xor_sync(0xFFFFFFFFu, mx[r], o));

    // ---- per row: double-precision (x - m), exp, sum, store ----
#pragma unroll
    for (int r = 0; r < ROWS_PER_WARP; ++r) {
        const int i = i0 + r * WARPS_PER_BLOCK;
        const double sc_d = (double)scale[r];
        const double m_d  = (double)mx[r];

        float4 t[16];
        float sum = 0.0f;
#pragma unroll
        for (int c = 0; c < 16; ++c) {
            const int idx = c * 32 + lane;
            const float4 sv = s4[idx];
            const double2 p0 = d2[2 * idx + 0];
            const double2 p1 = d2[2 * idx + 1];
            float4 tv;
            tv.x = __expf((float)(fma(sc_d, (double)sv.x, -p0.x) - m_d));
            tv.y = __expf((float)(fma(sc_d, (double)sv.y, -p0.y) - m_d));
            tv.z = __expf((float)(fma(sc_d, (double)sv.z, -p1.x) - m_d));
            tv.w = __expf((float)(fma(sc_d, (double)sv.w, -p1.y) - m_d));
            sum += (tv.x + tv.y) + (tv.z + tv.w);
            t[c] = tv;
        }
#pragma unroll
        for (int o = 16; o > 0; o >>= 1)
            sum += __shfl_xor_sync(0xFFFFFFFFu, sum, o);
        const float inv = __frcp_rn(sum);

        float4* o4 = (float4*)(out + ((size_t)b * NS_N + (size_t)i) * NS_N);
#pragma unroll
        for (int c = 0; c < 16; ++c) {
            float4 tv = t[c];
            tv.x *= inv;
            tv.y *= inv;
            tv.z *= inv;
            tv.w *= inv;
            o4[c * 32 + lane] = tv;
        }
    }
}

extern "C" void kernel_launch(void* const* d_in, const int* in_sizes, int n_in,
                              void* d_out, int out_size) {
    const float* scores = (const float*)d_in[0];
    float* out = (float*)d_out;
    (void)in_sizes; (void)n_in; (void)out_size;

    dim3 g1(NS_N / 256, NS_B);
    ns_bsum_kernel<<<g1, 256>>>(scores);

    dim3 g2(NS_N / ROWS_PER_BLOCK, NS_B);
    ns_softmax_kernel<<<g2, 256>>>(scores, out);
}

// round 3
// speedup vs baseline: 2.4324x; 2.4324x over previous
#include <cuda_runtime.h>
#include <math.h>

#define NS_N 2048
#define NS_B 16
#define K2_WARPS 8
#define K2_RPW 4
#define K2_ROWS (K2_WARPS * K2_RPW)   // 32 rows per block

// Bsum split into grid-2^-10 part + residual (allocation-free rule: __device__ globals)
__device__ float g_bhi[NS_B * NS_N];
__device__ float g_blo[NS_B * NS_N];

// ---------------------------------------------------------------------------
// Kernel 1: Bsum[b][j] = sum_k |s[b][j] - s[b][k]|
// One warp per j. Per-lane Kahan f32 over 64 terms, f64 warp reduce (5 DADDs).
// Output split: b_hi = round(B * 2^10)/2^10 (exactly representable on grid),
//               b_lo = B - b_hi (small residual).
// grid: (N/8, B), block 256 (8 warps)
// ---------------------------------------------------------------------------
__global__ __launch_bounds__(256) void ns_bsum_kernel(const float* __restrict__ scores) {
    __shared__ float s[NS_N];
    const int b = blockIdx.y;
    {
        const float4* sp4 = (const float4*)(scores + b * NS_N);
        float4* s4 = (float4*)s;
        for (int k = threadIdx.x; k < NS_N / 4; k += 256)
            s4[k] = sp4[k];
    }
    __syncthreads();

    const int warp = threadIdx.x >> 5;
    const int lane = threadIdx.x & 31;
    const int j = blockIdx.x * 8 + warp;
    const float sj = s[j];

    float sum = 0.0f, c = 0.0f;
#pragma unroll 8
    for (int t = 0; t < 64; ++t) {
        float x = fabsf(sj - s[lane + (t << 5)]);
        float y = x - c;
        float u = sum + y;
        c = (u - sum) - y;
        sum = u;
    }
    double d = (double)sum - (double)c;
#pragma unroll
    for (int o = 16; o > 0; o >>= 1)
        d += __shfl_xor_sync(0xFFFFFFFFu, d, o);

    if (lane == 0) {
        float bh = (float)__float2int_rn((float)d * 1024.0f) * (1.0f / 1024.0f);
        float bl = (float)(d - (double)bh);
        g_bhi[b * NS_N + j] = bh;
        g_blo[b * NS_N + j] = bl;
    }
}

// ---------------------------------------------------------------------------
// Kernel 2: out[b][i][j] = softmax_j( scale_i * s[b][j] - Bsum[b][j] )
// All-f32 exact-split arithmetic:
//   s_hi = s rounded to 2^-10 grid, s_lo = s - s_hi (exact)
//   h  = fmaf(sc, s_hi, -b_hi)   -- EXACT (grid value, <2^24)
//   l  = fmaf(sc, s_lo, -b_lo)   -- |l| <= ~1, ~1e-7 error
//   logit - m = (h - m) + l       (h - m exact where it matters)
// One warp per row, 4 rows/warp, exp values held in registers.
// grid: (N/32, B), block 256 (8 warps), 2 CTAs/SM via launch_bounds.
// ---------------------------------------------------------------------------
__global__ __launch_bounds__(256, 2) void ns_softmax_kernel(const float* __restrict__ scores,
                                                            float* __restrict__ out) {
    __shared__ float sh_sh[NS_N];
    __shared__ float sh_sl[NS_N];
    __shared__ float sh_bh[NS_N];
    __shared__ float sh_bl[NS_N];

    const int b = blockIdx.y;
    {
        const float4* sp4 = (const float4*)(scores + b * NS_N);
        const float4* bh4 = (const float4*)(g_bhi + b * NS_N);
        const float4* bl4 = (const float4*)(g_blo + b * NS_N);
        for (int k = threadIdx.x; k < NS_N / 4; k += 256) {
            float4 sv = sp4[k];
            float4 hv, lv;
            hv.x = (float)__float2int_rn(sv.x * 1024.0f) * (1.0f / 1024.0f); lv.x = sv.x - hv.x;
            hv.y = (float)__float2int_rn(sv.y * 1024.0f) * (1.0f / 1024.0f); lv.y = sv.y - hv.y;
            hv.z = (float)__float2int_rn(sv.z * 1024.0f) * (1.0f / 1024.0f); lv.z = sv.z - hv.z;
            hv.w = (float)__float2int_rn(sv.w * 1024.0f) * (1.0f / 1024.0f); lv.w = sv.w - hv.w;
            ((float4*)sh_sh)[k] = hv;
            ((float4*)sh_sl)[k] = lv;
            ((float4*)sh_bh)[k] = bh4[k];
            ((float4*)sh_bl)[k] = bl4[k];
        }
    }
    __syncthreads();

    const int warp = threadIdx.x >> 5;
    const int lane = threadIdx.x & 31;
    const float4* SH = (const float4*)sh_sh;
    const float4* SL = (const float4*)sh_sl;
    const float4* BH = (const float4*)sh_bh;
    const float4* BL = (const float4*)sh_bl;

    const int i0 = blockIdx.x * K2_ROWS + warp;     // rows: i0 + r*8
    float sc[K2_RPW], mx[K2_RPW];
#pragma unroll
    for (int r = 0; r < K2_RPW; ++r) {
        sc[r] = (float)(NS_N - 1 - 2 * (i0 + r * K2_WARPS));
        mx[r] = -INFINITY;
    }

    // ---- pass A: row maxima of h (exact grid values); loads shared by 4 rows
#pragma unroll
    for (int c = 0; c < 16; ++c) {
        const int idx = c * 32 + lane;
        const float4 hv = SH[idx];
        const float4 bv = BH[idx];
#pragma unroll
        for (int r = 0; r < K2_RPW; ++r) {
            const float s = sc[r];
            float h0 = fmaf(s, hv.x, -bv.x);
            float h1 = fmaf(s, hv.y, -bv.y);
            float h2 = fmaf(s, hv.z, -bv.z);
            float h3 = fmaf(s, hv.w, -bv.w);
            mx[r] = fmaxf(mx[r], fmaxf(fmaxf(h0, h1), fmaxf(h2, h3)));
        }
    }
#pragma unroll
    for (int r = 0; r < K2_RPW; ++r)
#pragma unroll
        for (int o = 16; o > 0; o >>= 1)
            mx[r] = fmaxf(mx[r], __shfl_xor_sync(0xFFFFFFFFu, mx[r], o));

    // ---- per row: exp (into registers), sum, normalize, store ----
#pragma unroll
    for (int r = 0; r < K2_RPW; ++r) {
        const int i = i0 + r * K2_WARPS;
        const float s = sc[r];
        const float m = mx[r];

        float4 t[16];
        float sum = 0.0f;
#pragma unroll
        for (int c = 0; c < 16; ++c) {
            const int idx = c * 32 + lane;
            const float4 hv = SH[idx];
            const float4 lv = SL[idx];
            const float4 bh = BH[idx];
            const float4 bl = BL[idx];
            float4 tv;
            tv.x = __expf((fmaf(s, hv.x, -bh.x) - m) + fmaf(s, lv.x, -bl.x));
            tv.y = __expf((fmaf(s, hv.y, -bh.y) - m) + fmaf(s, lv.y, -bl.y));
            tv.z = __expf((fmaf(s, hv.z, -bh.z) - m) + fmaf(s, lv.z, -bl.z));
            tv.w = __expf((fmaf(s, hv.w, -bh.w) - m) + fmaf(s, lv.w, -bl.w));
            sum += (tv.x + tv.y) + (tv.z + tv.w);
            t[c] = tv;
        }
#pragma unroll
        for (int o = 16; o > 0; o >>= 1)
            sum += __shfl_xor_sync(0xFFFFFFFFu, sum, o);
        const float inv = __frcp_rn(sum);

        float4* o4 = (float4*)(out + ((size_t)b * NS_N + (size_t)i) * NS_N);
#pragma unroll
        for (int c = 0; c < 16; ++c) {
            float4 tv = t[c];
            tv.x *= inv;
            tv.y *= inv;
            tv.z *= inv;
            tv.w *= inv;
            o4[c * 32 + lane] = tv;
        }
    }
}

extern "C" void kernel_launch(void* const* d_in, const int* in_sizes, int n_in,
                              void* d_out, int out_size) {
    const float* scores = (const float*)d_in[0];
    float* out = (float*)d_out;
    (void)in_sizes; (void)n_in; (void)out_size;

    dim3 g1(NS_N / 8, NS_B);
    ns_bsum_kernel<<<g1, 256>>>(scores);

    dim3 g2(NS_N / K2_ROWS, NS_B);
    ns_softmax_kernel<<<g2, 256>>>(scores, out);
}

// round 4
// speedup vs baseline: 4.2608x; 1.7517x over previous
#include <cuda_runtime.h>
#include <math.h>

#define NS_N 2048
#define NS_B 16

// log2e-domain split arrays (allocation-free rule: __device__ globals)
//   s' = s*log2e :  g_shi on 2^-10 grid, g_slo residual
//   B' = B*log2e :  g_nbh = -(grid part), g_nbl = -(residual)   [pre-negated]
__device__ float g_shi[NS_B * NS_N];
__device__ float g_slo[NS_B * NS_N];
__device__ float g_nbh[NS_B * NS_N];
__device__ float g_nbl[NS_B * NS_N];

// ---------------- f32x2 packed helpers (sm_103a) ----------------
typedef unsigned long long u64;
__device__ __forceinline__ u64 pk2(float x, float y) {
    u64 r; asm("mov.b64 %0, {%1,%2};" : "=l"(r) : "f"(x), "f"(y)); return r;
}
__device__ __forceinline__ float2 upk2(u64 v) {
    float2 r; asm("mov.b64 {%0,%1}, %2;" : "=f"(r.x), "=f"(r.y) : "l"(v)); return r;
}
__device__ __forceinline__ u64 fma2(u64 a, u64 b, u64 c) {
    u64 d; asm("fma.rn.f32x2 %0, %1, %2, %3;" : "=l"(d) : "l"(a), "l"(b), "l"(c)); return d;
}
__device__ __forceinline__ u64 add2(u64 a, u64 b) {
    u64 d; asm("add.rn.f32x2 %0, %1, %2;" : "=l"(d) : "l"(a), "l"(b)); return d;
}
__device__ __forceinline__ u64 mul2(u64 a, u64 b) {
    u64 d; asm("mul.rn.f32x2 %0, %1, %2;" : "=l"(d) : "l"(a), "l"(b)); return d;
}
__device__ __forceinline__ float ex2(float x) {
    float r; asm("ex2.approx.ftz.f32 %0, %1;" : "=f"(r) : "f"(x)); return r;
}

// ---------------------------------------------------------------------------
// Kernel 1: Bsum[b][j] = sum_k |s[b][j] - s[b][k]| (warp per j, Kahan f32 over
// pre-added pairs, f64 warp reduce). Lane 0 emits log2e-domain grid splits.
// grid: (N/8, B), block 256
// ---------------------------------------------------------------------------
__global__ __launch_bounds__(256) void ns_bsum_kernel(const float* __restrict__ scores) {
    __shared__ float s[NS_N];
    const int b = blockIdx.y;
    {
        const float4* sp4 = (const float4*)(scores + b * NS_N);
        float4* s4 = (float4*)s;
        for (int k = threadIdx.x; k < NS_N / 4; k += 256)
            s4[k] = sp4[k];
    }
    __syncthreads();

    const int warp = threadIdx.x >> 5;
    const int lane = threadIdx.x & 31;
    const int j = blockIdx.x * 8 + warp;
    const float sj = s[j];

    float sum = 0.0f, comp = 0.0f;
#pragma unroll 8
    for (int t = 0; t < 64; t += 2) {
        float x = fabsf(sj - s[lane + (t << 5)]) + fabsf(sj - s[lane + ((t + 1) << 5)]);
        float y = x - comp;
        float u = sum + y;
        comp = (u - sum) - y;
        sum = u;
    }
    double d = (double)sum - (double)comp;
#pragma unroll
    for (int o = 16; o > 0; o >>= 1)
        d += __shfl_xor_sync(0xFFFFFFFFu, d, o);

    if (lane == 0) {
        const double LOG2E = 1.4426950408889634074;
        double Bp = d * LOG2E;
        double gB = rint(Bp * 1024.0);
        float bh = (float)(gB * (1.0 / 1024.0));
        float bl = (float)(Bp - (double)bh);
        double sp = (double)sj * LOG2E;
        double gS = rint(sp * 1024.0);
        float sh = (float)(gS * (1.0 / 1024.0));
        float sl = (float)(sp - (double)sh);
        g_shi[b * NS_N + j] = sh;
        g_slo[b * NS_N + j] = sl;
        g_nbh[b * NS_N + j] = -bh;
        g_nbl[b * NS_N + j] = -bl;
    }
}

// ---------------------------------------------------------------------------
// Kernel 2: out[b][i][j] = softmax_j( scale_i * s[b][j] - Bsum[b][j] )
// Quarter-row warps: warp (q = w&3) handles elements [q*512,(q+1)*512) of
// rows ibase+0..3 (g = w>>2 selects row group). Cross-warp max/sum via SMEM.
// exp = ex2( (h - m) + l ), h exact on 2^-10 grid near the max.
// grid: (N/8, B), block 256, 4 CTAs/SM.
// ---------------------------------------------------------------------------
__global__ __launch_bounds__(256, 4) void ns_softmax_kernel(float* __restrict__ out) {
    __shared__ float4 SH[512], SL[512], NBH[512], NBL[512];
    __shared__ float red_max[32];   // [(g*4+r)*4 + q]
    __shared__ float red_sum[32];

    const int b = blockIdx.y;
    {
        const float4* p0 = (const float4*)(g_shi + b * NS_N);
        const float4* p1 = (const float4*)(g_slo + b * NS_N);
        const float4* p2 = (const float4*)(g_nbh + b * NS_N);
        const float4* p3 = (const float4*)(g_nbl + b * NS_N);
        for (int k = threadIdx.x; k < 512; k += 256) {
            SH[k] = p0[k]; SL[k] = p1[k]; NBH[k] = p2[k]; NBL[k] = p3[k];
        }
    }
    __syncthreads();

    const int warp = threadIdx.x >> 5;
    const int lane = threadIdx.x & 31;
    const int q = warp & 3;
    const int g = warp >> 2;
    const int ibase = blockIdx.x * 8 + g * 4;      // rows ibase .. ibase+3

    float sc[4], mx[4];
#pragma unroll
    for (int r = 0; r < 4; ++r) {
        sc[r] = (float)(NS_N - 1 - 2 * (ibase + r));
        mx[r] = -INFINITY;
    }

    // ---- pass A: quarter maxima (loads shared across 4 rows) ----
#pragma unroll
    for (int cc = 0; cc < 4; ++cc) {
        const int idx = q * 128 + cc * 32 + lane;
        const float4 sh4 = SH[idx];
        const float4 nb4 = NBH[idx];
#pragma unroll
        for (int r = 0; r < 4; ++r) {
            const float s = sc[r];
            float h0 = fmaf(s, sh4.x, nb4.x);
            float h1 = fmaf(s, sh4.y, nb4.y);
            float h2 = fmaf(s, sh4.z, nb4.z);
            float h3 = fmaf(s, sh4.w, nb4.w);
            mx[r] = fmaxf(mx[r], fmaxf(fmaxf(h0, h1), fmaxf(h2, h3)));
        }
    }
#pragma unroll
    for (int r = 0; r < 4; ++r)
#pragma unroll
        for (int o = 16; o > 0; o >>= 1)
            mx[r] = fmaxf(mx[r], __shfl_xor_sync(0xFFFFFFFFu, mx[r], o));
    if (lane == 0) {
#pragma unroll
        for (int r = 0; r < 4; ++r)
            red_max[(g * 4 + r) * 4 + q] = mx[r];
    }
    __syncthreads();

    float m[4];
#pragma unroll
    for (int r = 0; r < 4; ++r) {
        const int base = (g * 4 + r) * 4;
        m[r] = fmaxf(fmaxf(red_max[base], red_max[base + 1]),
                     fmaxf(red_max[base + 2], red_max[base + 3]));
    }

    // ---- per row: exp quarter into regs, cross-warp sum, store ----
#pragma unroll 1
    for (int r = 0; r < 4; ++r) {
        const u64 sc2 = pk2(sc[r], sc[r]);
        const u64 nm2 = pk2(-m[r], -m[r]);

        float4 t[4];
        u64 s01 = pk2(0.0f, 0.0f), s23 = pk2(0.0f, 0.0f);
#pragma unroll
        for (int cc = 0; cc < 4; ++cc) {
            const int idx = q * 128 + cc * 32 + lane;
            const float4 sh4 = SH[idx];
            const float4 sl4 = SL[idx];
            const float4 nbh4 = NBH[idx];
            const float4 nbl4 = NBL[idx];
            u64 h01 = fma2(sc2, pk2(sh4.x, sh4.y), pk2(nbh4.x, nbh4.y));
            u64 h23 = fma2(sc2, pk2(sh4.z, sh4.w), pk2(nbh4.z, nbh4.w));
            u64 l01 = fma2(sc2, pk2(sl4.x, sl4.y), pk2(nbl4.x, nbl4.y));
            u64 l23 = fma2(sc2, pk2(sl4.z, sl4.w), pk2(nbl4.z, nbl4.w));
            // (h - m) first (exact where it matters), then + l
            u64 a01 = add2(add2(h01, nm2), l01);
            u64 a23 = add2(add2(h23, nm2), l23);
            float2 f01 = upk2(a01), f23 = upk2(a23);
            float e0 = ex2(f01.x), e1 = ex2(f01.y), e2 = ex2(f23.x), e3 = ex2(f23.y);
            t[cc] = make_float4(e0, e1, e2, e3);
            s01 = add2(s01, pk2(e0, e1));
            s23 = add2(s23, pk2(e2, e3));
        }
        float2 sa = upk2(s01), sb = upk2(s23);
        float sum = (sa.x + sa.y) + (sb.x + sb.y);
#pragma unroll
        for (int o = 16; o > 0; o >>= 1)
            sum += __shfl_xor_sync(0xFFFFFFFFu, sum, o);
        if (lane == 0)
            red_sum[(g * 4 + r) * 4 + q] = sum;
        __syncthreads();

        const int base = (g * 4 + r) * 4;
        const float tot = (red_sum[base] + red_sum[base + 1]) +
                          (red_sum[base + 2] + red_sum[base + 3]);
        const float inv = __frcp_rn(tot);
        const u64 inv2 = pk2(inv, inv);

        float4* o4 = (float4*)(out + ((size_t)b * NS_N + (size_t)(ibase + r)) * NS_N);
#pragma unroll
        for (int cc = 0; cc < 4; ++cc) {
            const float4 tv = t[cc];
            float2 r01 = upk2(mul2(pk2(tv.x, tv.y), inv2));
            float2 r23 = upk2(mul2(pk2(tv.z, tv.w), inv2));
            o4[q * 128 + cc * 32 + lane] = make_float4(r01.x, r01.y, r23.x, r23.y);
        }
    }
}

extern "C" void kernel_launch(void* const* d_in, const int* in_sizes, int n_in,
                              void* d_out, int out_size) {
    const float* scores = (const float*)d_in[0];
    float* out = (float*)d_out;
    (void)in_sizes; (void)n_in; (void)out_size;

    dim3 g1(NS_N / 8, NS_B);
    ns_bsum_kernel<<<g1, 256>>>(scores);

    dim3 g2(NS_N / 8, NS_B);
    ns_softmax_kernel<<<g2, 256>>>(out);
}